// round 7
// baseline (speedup 1.0000x reference)
#include <cuda_runtime.h>
#include <cuda_fp16.h>

// Problem constants (fixed by the dataset)
#define NN    50000
#define E0C   800000
#define HEADS 16
#define HD    8
#define HIDD  128

// ---------------- scratch (device globals, no allocation) ----------------
__device__ __align__(16) __half g_xh16[NN * HIDD];  // fp16 copy of x @ W (message path)
__device__ __align__(16) float  g_h[NN * HIDD];     // layer-1 output (layer-2 input)
__device__ __align__(16) float  g_als[NN * HEADS];
__device__ __align__(16) float  g_ald[NN * HEADS];

// CSR (by dst), built once per call
__device__ int g_deg[NN];
__device__ int g_off[NN + 1];
__device__ int g_cur[NN];
__device__ int g_srclist[E0C];

// ---------------- CSR build -------------------------------------------------
__global__ void csr_zero_kernel() {
    int n = blockIdx.x * blockDim.x + threadIdx.x;
    if (n < NN) g_deg[n] = 0;
}

__global__ void csr_hist_kernel(const int* __restrict__ ei) {
    int e = blockIdx.x * blockDim.x + threadIdx.x;
    if (e >= E0C) return;
    atomicAdd(&g_deg[__ldg(ei + E0C + e)], 1);
}

// single-block exclusive scan over NN degrees
__global__ void csr_scan_kernel() {
    __shared__ int partial[1024];
    const int t = threadIdx.x;
    const int CH = (NN + 1023) / 1024;   // 49
    const int start = t * CH;

    int sum = 0;
    for (int i = 0; i < CH; i++) {
        int n = start + i;
        if (n < NN) sum += g_deg[n];
    }
    partial[t] = sum;
    __syncthreads();
    for (int off = 1; off < 1024; off <<= 1) {
        int v = (t >= off) ? partial[t - off] : 0;
        __syncthreads();
        partial[t] += v;
        __syncthreads();
    }
    int run = (t == 0) ? 0 : partial[t - 1];
    for (int i = 0; i < CH; i++) {
        int n = start + i;
        if (n < NN) {
            g_off[n] = run;
            g_cur[n] = run;
            run += g_deg[n];
        }
    }
    if (t == 1023) g_off[NN] = run;
}

__global__ void csr_scatter_kernel(const int* __restrict__ ei) {
    int e = blockIdx.x * blockDim.x + threadIdx.x;
    if (e >= E0C) return;
    int src = __ldg(ei + e);
    int dst = __ldg(ei + E0C + e);
    int pos = atomicAdd(&g_cur[dst], 1);
    g_srclist[pos] = src;
}

// ---------------- tf32 tensor-core GEMM + fused logits + fp16 store --------
#define WS_PITCH 136   // words; 136 % 32 == 8 -> conflict-free frag loads
#define GEMM_ROWS 128
#define GEMM_SMEM_BYTES ((128 * WS_PITCH + 8 * WS_PITCH) * 4)

__device__ __forceinline__ unsigned f2tf32(float f) {
    unsigned r;
    asm("cvt.rna.tf32.f32 %0, %1;" : "=r"(r) : "f"(f));
    return r;
}

__device__ __forceinline__ void mma_tf32(float& d0, float& d1, float& d2, float& d3,
                                         unsigned a0, unsigned a1, unsigned a2, unsigned a3,
                                         unsigned b0, unsigned b1) {
    asm volatile(
        "mma.sync.aligned.m16n8k8.row.col.f32.tf32.tf32.f32 "
        "{%0,%1,%2,%3},{%4,%5,%6,%7},{%8,%9},{%0,%1,%2,%3};"
        : "+f"(d0), "+f"(d1), "+f"(d2), "+f"(d3)
        : "r"(a0), "r"(a1), "r"(a2), "r"(a3), "r"(b0), "r"(b1));
}

template <int LAYER>
__global__ void gemm_kernel(const float* __restrict__ X,
                            const float* __restrict__ W,
                            const float* __restrict__ a_src,
                            const float* __restrict__ a_dst, int M) {
    const float* A = (LAYER == 0) ? X : g_h;

    extern __shared__ unsigned smem_u[];
    unsigned* Ws  = smem_u;                    // [128][WS_PITCH] tf32 W (k-major)
    unsigned* Ast = smem_u + 128 * WS_PITCH;   // [8][WS_PITCH] tf32 A^T per k-step

    const int tid  = threadIdx.x;   // 256
    const int lane = tid & 31;
    const int w    = tid >> 5;      // warp 0..7
    const int g    = lane >> 2;     // group 0..7
    const int t    = lane & 3;      // thread-in-group 0..3
    const int row0 = blockIdx.x * GEMM_ROWS;

    // ---- stage W (convert to tf32), 16 float4 per thread ----
#pragma unroll
    for (int it = 0; it < 16; it++) {
        int v = tid + it * 256;          // 0..4095
        int k = v >> 5;
        int n4 = (v & 31) << 2;
        float4 wv = *reinterpret_cast<const float4*>(W + (size_t)k * HIDD + n4);
        unsigned* p = Ws + k * WS_PITCH + n4;
        p[0] = f2tf32(wv.x); p[1] = f2tf32(wv.y);
        p[2] = f2tf32(wv.z); p[3] = f2tf32(wv.w);
    }
    __syncthreads();

    float acc[16][4];
#pragma unroll
    for (int j = 0; j < 16; j++)
#pragma unroll
        for (int c = 0; c < 4; c++) acc[j][c] = 0.f;

    // ---- main K loop: 16 steps of k=8 ----
    for (int ks = 0; ks < 16; ks++) {
        const int k0 = ks * 8;
        {
            int r = tid >> 1;
            int c4 = (tid & 1) << 2;
            int grow = row0 + r;
            float4 av = make_float4(0.f, 0.f, 0.f, 0.f);
            if (grow < M)
                av = *reinterpret_cast<const float4*>(A + (size_t)grow * HIDD + k0 + c4);
            Ast[(c4 + 0) * WS_PITCH + r] = f2tf32(av.x);
            Ast[(c4 + 1) * WS_PITCH + r] = f2tf32(av.y);
            Ast[(c4 + 2) * WS_PITCH + r] = f2tf32(av.z);
            Ast[(c4 + 3) * WS_PITCH + r] = f2tf32(av.w);
        }
        __syncthreads();

        unsigned a0 = Ast[t * WS_PITCH + 16 * w + g];
        unsigned a1 = Ast[t * WS_PITCH + 16 * w + g + 8];
        unsigned a2 = Ast[(t + 4) * WS_PITCH + 16 * w + g];
        unsigned a3 = Ast[(t + 4) * WS_PITCH + 16 * w + g + 8];
        const unsigned* wb0 = Ws + (k0 + t) * WS_PITCH + g;
        const unsigned* wb1 = Ws + (k0 + t + 4) * WS_PITCH + g;
#pragma unroll
        for (int j = 0; j < 16; j++) {
            unsigned b0 = wb0[8 * j];
            unsigned b1 = wb1[8 * j];
            mma_tf32(acc[j][0], acc[j][1], acc[j][2], acc[j][3],
                     a0, a1, a2, a3, b0, b1);
        }
        __syncthreads();
    }

    // ---- epilogue: fp16 store + per-head logits ----
    const int rw = row0 + 16 * w;
#pragma unroll
    for (int j = 0; j < 16; j++) {
        float c0 = acc[j][0], c1 = acc[j][1], c2 = acc[j][2], c3 = acc[j][3];
        int colb = 8 * j + 2 * t;
        float2 sv = __ldg(reinterpret_cast<const float2*>(a_src + colb));
        float2 dv = __ldg(reinterpret_cast<const float2*>(a_dst + colb));
        float s0 = c0 * sv.x + c1 * sv.y;
        float d0 = c0 * dv.x + c1 * dv.y;
        float s1 = c2 * sv.x + c3 * sv.y;
        float d1 = c2 * dv.x + c3 * dv.y;
        s0 += __shfl_xor_sync(0xffffffffu, s0, 1);
        s0 += __shfl_xor_sync(0xffffffffu, s0, 2);
        d0 += __shfl_xor_sync(0xffffffffu, d0, 1);
        d0 += __shfl_xor_sync(0xffffffffu, d0, 2);
        s1 += __shfl_xor_sync(0xffffffffu, s1, 1);
        s1 += __shfl_xor_sync(0xffffffffu, s1, 2);
        d1 += __shfl_xor_sync(0xffffffffu, d1, 1);
        d1 += __shfl_xor_sync(0xffffffffu, d1, 2);

        int r0v = rw + g, r1v = rw + g + 8;
        if (r0v < M) {
            __half2 p = __floats2half2_rn(c0, c1);
            *reinterpret_cast<__half2*>(g_xh16 + (size_t)r0v * HIDD + colb) = p;
            if (t == 0) {
                g_als[r0v * HEADS + j] = s0;
                g_ald[r0v * HEADS + j] = d0;
            }
        }
        if (r1v < M) {
            __half2 p = __floats2half2_rn(c2, c3);
            *reinterpret_cast<__half2*>(g_xh16 + (size_t)r1v * HIDD + colb) = p;
            if (t == 0) {
                g_als[r1v * HEADS + j] = s1;
                g_ald[r1v * HEADS + j] = d1;
            }
        }
    }
}

// ---------------- fused aggregation: 4 warps per node ----------------------
// Block = 256 threads = 2 node-groups of 128. Within a group, the 4 warps
// split the neighbor list into contiguous quarters (serial chain /4), each
// accumulating in registers; smem combine; warp 0 normalizes + bias (+ELU).
__device__ __forceinline__ void load_msg4(const __half* base, int lane,
                                          float& f0, float& f1, float& f2, float& f3) {
    uint2 raw = __ldg(reinterpret_cast<const uint2*>(base + lane * 4));
    __half2 h0 = *reinterpret_cast<__half2*>(&raw.x);
    __half2 h1 = *reinterpret_cast<__half2*>(&raw.y);
    float2 a = __half22float2(h0);
    float2 b = __half22float2(h1);
    f0 = a.x; f1 = a.y; f2 = b.x; f3 = b.y;
}

template <int LAYER>
__global__ void aggregate_kernel(const float* __restrict__ bias,
                                 float* __restrict__ outbuf) {
    __shared__ float red[2][3][32][5];   // [group][warp 1..3][lane][acc0..3,denom]

    const int tid  = threadIdx.x;
    const int grp  = tid >> 7;                 // node group 0..1
    const int wg   = (tid >> 5) & 3;           // warp within group
    const int lane = tid & 31;
    const int n = blockIdx.x * 2 + grp;        // NN even; always valid
    const int h = lane >> 1;

    const float ald_h = __ldg(g_ald + n * HEADS + h);

    float acc0 = 0.f, acc1 = 0.f, acc2 = 0.f, acc3 = 0.f, denom = 0.f;

    // self loop handled by warp 0
    if (wg == 0) {
        float v = __ldg(g_als + n * HEADS + h) + ald_h;
        float lr = v > 0.f ? v : 0.2f * v;
        float ex = __expf(lr);
        float f0, f1, f2, f3;
        load_msg4(g_xh16 + (size_t)n * HIDD, lane, f0, f1, f2, f3);
        acc0 = ex * f0; acc1 = ex * f1; acc2 = ex * f2; acc3 = ex * f3;
        denom = ex;
    }

    const int beg = __ldg(g_off + n);
    const int end = __ldg(g_off + n + 1);
    const int chunk = (end - beg + 3) >> 2;
    const int b = beg + wg * chunk;
    const int e = min(b + chunk, end);

    for (int j0 = b; j0 < e; j0 += 32) {
        int myidx = j0 + lane;
        int s = (myidx < e) ? __ldg(g_srclist + myidx) : 0;
        int cnt = min(32, e - j0);
#pragma unroll 4
        for (int k = 0; k < cnt; k++) {
            int src = __shfl_sync(0xffffffffu, s, k);
            float v = __ldg(g_als + src * HEADS + h) + ald_h;
            float lr = v > 0.f ? v : 0.2f * v;
            float ex = __expf(lr);
            float f0, f1, f2, f3;
            load_msg4(g_xh16 + (size_t)src * HIDD, lane, f0, f1, f2, f3);
            acc0 = fmaf(ex, f0, acc0);
            acc1 = fmaf(ex, f1, acc1);
            acc2 = fmaf(ex, f2, acc2);
            acc3 = fmaf(ex, f3, acc3);
            denom += ex;
        }
    }

    // combine partials: warps 1..3 -> smem, warp 0 reduces + finalizes
    if (wg > 0) {
        float* p = red[grp][wg - 1][lane];
        p[0] = acc0; p[1] = acc1; p[2] = acc2; p[3] = acc3; p[4] = denom;
    }
    __syncthreads();
    if (wg == 0) {
#pragma unroll
        for (int w2 = 0; w2 < 3; w2++) {
            const float* p = red[grp][w2][lane];
            acc0 += p[0]; acc1 += p[1]; acc2 += p[2]; acc3 += p[3]; denom += p[4];
        }
        float inv = 1.f / (denom + 1e-16f);
        float4 bv = *reinterpret_cast<const float4*>(bias + lane * 4);
        float4 r;
        r.x = acc0 * inv + bv.x;
        r.y = acc1 * inv + bv.y;
        r.z = acc2 * inv + bv.z;
        r.w = acc3 * inv + bv.w;
        if (LAYER == 0) {
            r.x = r.x > 0.f ? r.x : expm1f(r.x);
            r.y = r.y > 0.f ? r.y : expm1f(r.y);
            r.z = r.z > 0.f ? r.z : expm1f(r.z);
            r.w = r.w > 0.f ? r.w : expm1f(r.w);
            *reinterpret_cast<float4*>(g_h + (size_t)n * HIDD + lane * 4) = r;
        } else {
            *reinterpret_cast<float4*>(outbuf + (size_t)n * HIDD + lane * 4) = r;
        }
    }
}

// ---------------- launch ------------------------------------------------------
extern "C" void kernel_launch(void* const* d_in, const int* in_sizes, int n_in,
                              void* d_out, int out_size) {
    const float* x   = (const float*)d_in[0];
    const int*   ei  = (const int*)d_in[1];
    const float* W1  = (const float*)d_in[2];
    const float* as1 = (const float*)d_in[3];
    const float* ad1 = (const float*)d_in[4];
    const float* b1  = (const float*)d_in[5];
    const float* W2  = (const float*)d_in[6];
    const float* as2 = (const float*)d_in[7];
    const float* ad2 = (const float*)d_in[8];
    const float* b2  = (const float*)d_in[9];
    float* out = (float*)d_out;

    cudaFuncSetAttribute(gemm_kernel<0>, cudaFuncAttributeMaxDynamicSharedMemorySize,
                         GEMM_SMEM_BYTES);
    cudaFuncSetAttribute(gemm_kernel<1>, cudaFuncAttributeMaxDynamicSharedMemorySize,
                         GEMM_SMEM_BYTES);

    const int TB = 256;
    const int gGemm = (NN + GEMM_ROWS - 1) / GEMM_ROWS;
    const int gEdge = (E0C + TB - 1) / TB;
    const int gNode = (NN + TB - 1) / TB;
    const int gAgg  = NN / 2;                 // 2 nodes per block, 4 warps each

    // ---- CSR build (once; shared by both layers) ----
    csr_zero_kernel<<<gNode, TB>>>();
    csr_hist_kernel<<<gEdge, TB>>>(ei);
    csr_scan_kernel<<<1, 1024>>>();
    csr_scatter_kernel<<<gEdge, TB>>>(ei);

    // ---- layer 1 ----
    gemm_kernel<0><<<gGemm, TB, GEMM_SMEM_BYTES>>>(x, W1, as1, ad1, NN);
    aggregate_kernel<0><<<gAgg, TB>>>(b1, nullptr);

    // ---- layer 2 ----
    gemm_kernel<1><<<gGemm, TB, GEMM_SMEM_BYTES>>>(nullptr, W2, as2, ad2, NN);
    aggregate_kernel<1><<<gAgg, TB>>>(b2, out);
}

// round 8
// speedup vs baseline: 1.1444x; 1.1444x over previous
#include <cuda_runtime.h>
#include <cuda_fp16.h>

// Problem constants (fixed by the dataset)
#define NN    50000
#define E0C   800000
#define HEADS 16
#define HD    8
#define HIDD  128

// ---------------- scratch (device globals, no allocation) ----------------
__device__ __align__(16) __half g_xh16[NN * HIDD];  // fp16 copy of x @ W (message path)
__device__ __align__(16) float  g_h[NN * HIDD];     // layer-1 output (layer-2 input)
__device__ __align__(16) float  g_als[NN * HEADS];
__device__ __align__(16) float  g_ald[NN * HEADS];

// CSR (by dst), built once per call
__device__ int g_deg[NN];
__device__ int g_off[NN + 1];
__device__ int g_cur[NN];
__device__ int g_srclist[E0C];

// ---------------- CSR build -------------------------------------------------
__global__ void csr_zero_kernel() {
    int n = blockIdx.x * blockDim.x + threadIdx.x;
    if (n < NN) g_deg[n] = 0;
}

__global__ void csr_hist_kernel(const int* __restrict__ ei) {
    int e = blockIdx.x * blockDim.x + threadIdx.x;
    if (e >= E0C) return;
    atomicAdd(&g_deg[__ldg(ei + E0C + e)], 1);
}

// single-block exclusive scan over NN degrees
__global__ void csr_scan_kernel() {
    __shared__ int partial[1024];
    const int t = threadIdx.x;
    const int CH = (NN + 1023) / 1024;   // 49
    const int start = t * CH;

    int sum = 0;
    for (int i = 0; i < CH; i++) {
        int n = start + i;
        if (n < NN) sum += g_deg[n];
    }
    partial[t] = sum;
    __syncthreads();
    for (int off = 1; off < 1024; off <<= 1) {
        int v = (t >= off) ? partial[t - off] : 0;
        __syncthreads();
        partial[t] += v;
        __syncthreads();
    }
    int run = (t == 0) ? 0 : partial[t - 1];
    for (int i = 0; i < CH; i++) {
        int n = start + i;
        if (n < NN) {
            g_off[n] = run;
            g_cur[n] = run;
            run += g_deg[n];
        }
    }
    if (t == 1023) g_off[NN] = run;
}

__global__ void csr_scatter_kernel(const int* __restrict__ ei) {
    int e = blockIdx.x * blockDim.x + threadIdx.x;
    if (e >= E0C) return;
    int src = __ldg(ei + e);
    int dst = __ldg(ei + E0C + e);
    int pos = atomicAdd(&g_cur[dst], 1);
    g_srclist[pos] = src;
}

// ---------------- tf32 tensor-core GEMM + fused logits + fp16 store --------
#define WS_PITCH 136   // words; 136 % 32 == 8 -> conflict-free frag loads
#define GEMM_ROWS 128
#define GEMM_SMEM_BYTES ((128 * WS_PITCH + 8 * WS_PITCH) * 4)

__device__ __forceinline__ unsigned f2tf32(float f) {
    unsigned r;
    asm("cvt.rna.tf32.f32 %0, %1;" : "=r"(r) : "f"(f));
    return r;
}

__device__ __forceinline__ void mma_tf32(float& d0, float& d1, float& d2, float& d3,
                                         unsigned a0, unsigned a1, unsigned a2, unsigned a3,
                                         unsigned b0, unsigned b1) {
    asm volatile(
        "mma.sync.aligned.m16n8k8.row.col.f32.tf32.tf32.f32 "
        "{%0,%1,%2,%3},{%4,%5,%6,%7},{%8,%9},{%0,%1,%2,%3};"
        : "+f"(d0), "+f"(d1), "+f"(d2), "+f"(d3)
        : "r"(a0), "r"(a1), "r"(a2), "r"(a3), "r"(b0), "r"(b1));
}

template <int LAYER>
__global__ void gemm_kernel(const float* __restrict__ X,
                            const float* __restrict__ W,
                            const float* __restrict__ a_src,
                            const float* __restrict__ a_dst, int M) {
    const float* A = (LAYER == 0) ? X : g_h;

    extern __shared__ unsigned smem_u[];
    unsigned* Ws  = smem_u;                    // [128][WS_PITCH] tf32 W (k-major)
    unsigned* Ast = smem_u + 128 * WS_PITCH;   // [8][WS_PITCH] tf32 A^T per k-step

    const int tid  = threadIdx.x;   // 256
    const int lane = tid & 31;
    const int w    = tid >> 5;      // warp 0..7
    const int g    = lane >> 2;     // group 0..7
    const int t    = lane & 3;      // thread-in-group 0..3
    const int row0 = blockIdx.x * GEMM_ROWS;

    // ---- stage W (convert to tf32), 16 float4 per thread ----
#pragma unroll
    for (int it = 0; it < 16; it++) {
        int v = tid + it * 256;          // 0..4095
        int k = v >> 5;
        int n4 = (v & 31) << 2;
        float4 wv = *reinterpret_cast<const float4*>(W + (size_t)k * HIDD + n4);
        unsigned* p = Ws + k * WS_PITCH + n4;
        p[0] = f2tf32(wv.x); p[1] = f2tf32(wv.y);
        p[2] = f2tf32(wv.z); p[3] = f2tf32(wv.w);
    }
    __syncthreads();

    float acc[16][4];
#pragma unroll
    for (int j = 0; j < 16; j++)
#pragma unroll
        for (int c = 0; c < 4; c++) acc[j][c] = 0.f;

    // ---- main K loop: 16 steps of k=8 ----
    for (int ks = 0; ks < 16; ks++) {
        const int k0 = ks * 8;
        {
            int r = tid >> 1;
            int c4 = (tid & 1) << 2;
            int grow = row0 + r;
            float4 av = make_float4(0.f, 0.f, 0.f, 0.f);
            if (grow < M)
                av = *reinterpret_cast<const float4*>(A + (size_t)grow * HIDD + k0 + c4);
            Ast[(c4 + 0) * WS_PITCH + r] = f2tf32(av.x);
            Ast[(c4 + 1) * WS_PITCH + r] = f2tf32(av.y);
            Ast[(c4 + 2) * WS_PITCH + r] = f2tf32(av.z);
            Ast[(c4 + 3) * WS_PITCH + r] = f2tf32(av.w);
        }
        __syncthreads();

        unsigned a0 = Ast[t * WS_PITCH + 16 * w + g];
        unsigned a1 = Ast[t * WS_PITCH + 16 * w + g + 8];
        unsigned a2 = Ast[(t + 4) * WS_PITCH + 16 * w + g];
        unsigned a3 = Ast[(t + 4) * WS_PITCH + 16 * w + g + 8];
        const unsigned* wb0 = Ws + (k0 + t) * WS_PITCH + g;
        const unsigned* wb1 = Ws + (k0 + t + 4) * WS_PITCH + g;
#pragma unroll
        for (int j = 0; j < 16; j++) {
            unsigned b0 = wb0[8 * j];
            unsigned b1 = wb1[8 * j];
            mma_tf32(acc[j][0], acc[j][1], acc[j][2], acc[j][3],
                     a0, a1, a2, a3, b0, b1);
        }
        __syncthreads();
    }

    // ---- epilogue: fp16 store + per-head logits ----
    const int rw = row0 + 16 * w;
#pragma unroll
    for (int j = 0; j < 16; j++) {
        float c0 = acc[j][0], c1 = acc[j][1], c2 = acc[j][2], c3 = acc[j][3];
        int colb = 8 * j + 2 * t;
        float2 sv = __ldg(reinterpret_cast<const float2*>(a_src + colb));
        float2 dv = __ldg(reinterpret_cast<const float2*>(a_dst + colb));
        float s0 = c0 * sv.x + c1 * sv.y;
        float d0 = c0 * dv.x + c1 * dv.y;
        float s1 = c2 * sv.x + c3 * sv.y;
        float d1 = c2 * dv.x + c3 * dv.y;
        s0 += __shfl_xor_sync(0xffffffffu, s0, 1);
        s0 += __shfl_xor_sync(0xffffffffu, s0, 2);
        d0 += __shfl_xor_sync(0xffffffffu, d0, 1);
        d0 += __shfl_xor_sync(0xffffffffu, d0, 2);
        s1 += __shfl_xor_sync(0xffffffffu, s1, 1);
        s1 += __shfl_xor_sync(0xffffffffu, s1, 2);
        d1 += __shfl_xor_sync(0xffffffffu, d1, 1);
        d1 += __shfl_xor_sync(0xffffffffu, d1, 2);

        int r0v = rw + g, r1v = rw + g + 8;
        if (r0v < M) {
            __half2 p = __floats2half2_rn(c0, c1);
            *reinterpret_cast<__half2*>(g_xh16 + (size_t)r0v * HIDD + colb) = p;
            if (t == 0) {
                g_als[r0v * HEADS + j] = s0;
                g_ald[r0v * HEADS + j] = d0;
            }
        }
        if (r1v < M) {
            __half2 p = __floats2half2_rn(c2, c3);
            *reinterpret_cast<__half2*>(g_xh16 + (size_t)r1v * HIDD + colb) = p;
            if (t == 0) {
                g_als[r1v * HEADS + j] = s1;
                g_ald[r1v * HEADS + j] = d1;
            }
        }
    }
}

// ---------------- fused aggregation: half-warp per neighbor ----------------
// One warp per dst node. Lane l: hl = l&15 = head index; lane owns that
// head's 8 output cols. Lanes 0-15 process even neighbors, 16-31 odd
// (serial chain /2, no cross-warp overhead). shfl_down(16) combine at end.
__device__ __forceinline__ void load_msg8(const __half* p, float* f) {
    uint4 raw = __ldg(reinterpret_cast<const uint4*>(p));
    const __half2* h = reinterpret_cast<const __half2*>(&raw);
#pragma unroll
    for (int i = 0; i < 4; i++) {
        float2 v = __half22float2(h[i]);
        f[2 * i]     = v.x;
        f[2 * i + 1] = v.y;
    }
}

template <int LAYER>
__global__ void aggregate_kernel(const float* __restrict__ bias,
                                 float* __restrict__ outbuf) {
    const int warp = (blockIdx.x * blockDim.x + threadIdx.x) >> 5;
    if (warp >= NN) return;
    const int lane = threadIdx.x & 31;
    const int hl   = lane & 15;        // head owned by this lane
    const int odd  = lane >> 4;        // 0: even neighbors, 1: odd neighbors
    const int n = warp;

    const float ald_h = __ldg(g_ald + n * HEADS + hl);

    float acc[8];
    float denom;

    // self loop: group A only (group B starts at zero via ex=0)
    {
        float v = __ldg(g_als + n * HEADS + hl) + ald_h;
        float lr = v > 0.f ? v : 0.2f * v;
        float ex = odd ? 0.f : __expf(lr);
        float f[8];
        load_msg8(g_xh16 + (size_t)n * HIDD + hl * 8, f);
#pragma unroll
        for (int i = 0; i < 8; i++) acc[i] = ex * f[i];
        denom = ex;
    }

    const int beg = __ldg(g_off + n);
    const int end = __ldg(g_off + n + 1);
    const int deg = end - beg;

    for (int j0 = 0; j0 < deg; j0 += 32) {
        int myidx = beg + j0 + lane;
        int s = (myidx < end) ? __ldg(g_srclist + myidx) : 0;
        int cnt = min(32, deg - j0);
#pragma unroll 4
        for (int k = 0; k < cnt; k += 2) {
            int pick = k + odd;
            int src = __shfl_sync(0xffffffffu, s, pick & 31);
            bool valid = pick < cnt;
            float v = __ldg(g_als + src * HEADS + hl) + ald_h;
            float lr = v > 0.f ? v : 0.2f * v;
            float ex = valid ? __expf(lr) : 0.f;
            float f[8];
            load_msg8(g_xh16 + (size_t)src * HIDD + hl * 8, f);
#pragma unroll
            for (int i = 0; i < 8; i++) acc[i] = fmaf(ex, f[i], acc[i]);
            denom += ex;
        }
    }

    // combine the two half-warps: lane hl += lane hl+16
#pragma unroll
    for (int i = 0; i < 8; i++)
        acc[i] += __shfl_down_sync(0xffffffffu, acc[i], 16);
    denom += __shfl_down_sync(0xffffffffu, denom, 16);

    if (!odd) {
        float inv = 1.f / (denom + 1e-16f);
        float4 b0 = *reinterpret_cast<const float4*>(bias + hl * 8);
        float4 b1 = *reinterpret_cast<const float4*>(bias + hl * 8 + 4);
        float4 r0, r1;
        r0.x = acc[0] * inv + b0.x;
        r0.y = acc[1] * inv + b0.y;
        r0.z = acc[2] * inv + b0.z;
        r0.w = acc[3] * inv + b0.w;
        r1.x = acc[4] * inv + b1.x;
        r1.y = acc[5] * inv + b1.y;
        r1.z = acc[6] * inv + b1.z;
        r1.w = acc[7] * inv + b1.w;
        if (LAYER == 0) {
            r0.x = r0.x > 0.f ? r0.x : expm1f(r0.x);
            r0.y = r0.y > 0.f ? r0.y : expm1f(r0.y);
            r0.z = r0.z > 0.f ? r0.z : expm1f(r0.z);
            r0.w = r0.w > 0.f ? r0.w : expm1f(r0.w);
            r1.x = r1.x > 0.f ? r1.x : expm1f(r1.x);
            r1.y = r1.y > 0.f ? r1.y : expm1f(r1.y);
            r1.z = r1.z > 0.f ? r1.z : expm1f(r1.z);
            r1.w = r1.w > 0.f ? r1.w : expm1f(r1.w);
            *reinterpret_cast<float4*>(g_h + (size_t)n * HIDD + hl * 8)     = r0;
            *reinterpret_cast<float4*>(g_h + (size_t)n * HIDD + hl * 8 + 4) = r1;
        } else {
            *reinterpret_cast<float4*>(outbuf + (size_t)n * HIDD + hl * 8)     = r0;
            *reinterpret_cast<float4*>(outbuf + (size_t)n * HIDD + hl * 8 + 4) = r1;
        }
    }
}

// ---------------- launch ------------------------------------------------------
extern "C" void kernel_launch(void* const* d_in, const int* in_sizes, int n_in,
                              void* d_out, int out_size) {
    const float* x   = (const float*)d_in[0];
    const int*   ei  = (const int*)d_in[1];
    const float* W1  = (const float*)d_in[2];
    const float* as1 = (const float*)d_in[3];
    const float* ad1 = (const float*)d_in[4];
    const float* b1  = (const float*)d_in[5];
    const float* W2  = (const float*)d_in[6];
    const float* as2 = (const float*)d_in[7];
    const float* ad2 = (const float*)d_in[8];
    const float* b2  = (const float*)d_in[9];
    float* out = (float*)d_out;

    cudaFuncSetAttribute(gemm_kernel<0>, cudaFuncAttributeMaxDynamicSharedMemorySize,
                         GEMM_SMEM_BYTES);
    cudaFuncSetAttribute(gemm_kernel<1>, cudaFuncAttributeMaxDynamicSharedMemorySize,
                         GEMM_SMEM_BYTES);

    const int TB = 256;
    const int gGemm = (NN + GEMM_ROWS - 1) / GEMM_ROWS;
    const int gEdge = (E0C + TB - 1) / TB;
    const int gNode = (NN + TB - 1) / TB;
    const int gAgg  = (NN * 32 + TB - 1) / TB;   // one warp per node

    // ---- CSR build (once; shared by both layers) ----
    csr_zero_kernel<<<gNode, TB>>>();
    csr_hist_kernel<<<gEdge, TB>>>(ei);
    csr_scan_kernel<<<1, 1024>>>();
    csr_scatter_kernel<<<gEdge, TB>>>(ei);

    // ---- layer 1 ----
    gemm_kernel<0><<<gGemm, TB, GEMM_SMEM_BYTES>>>(x, W1, as1, ad1, NN);
    aggregate_kernel<0><<<gAgg, TB>>>(b1, nullptr);

    // ---- layer 2 ----
    gemm_kernel<1><<<gGemm, TB, GEMM_SMEM_BYTES>>>(nullptr, W2, as2, ad2, NN);
    aggregate_kernel<1><<<gAgg, TB>>>(b2, out);
}